// round 8
// baseline (speedup 1.0000x reference)
#include <cuda_runtime.h>
#include <math.h>

typedef unsigned long long ULL;

// ---------------------------------------------------------------------------
// B=16, dim=48, hid=16, C=8, H=W=256, HW=65536.
// Fused single kernel: block = (b, 8-row tile); 256 threads = 256 columns.
// Stage-A (GEMM1+gelu^2+LN) streams rows h0-1..h0+8 into a 4-slot smem ring;
// stage-B (dw3x3 + pw + gate + GEMM2) consumes rows ro-1..ro+1 per output row.
// x1 (gate) lives in registers: thread t's stage-B pixel is its own column.
// ---------------------------------------------------------------------------
#define HW 65536
#define NB 16

// Weights in constant memory (compile-time-indexed -> LDCU uniform port)
__constant__ ULL   cW1p[384];   // W1 (48,16) as pairs [k*8 + j2]
__constant__ ULL   cW2p[192];   // W2 (8,48)  as pairs [c*24 + d2]
__constant__ float cdw[72];     // dw_w (8,1,3,3)
__constant__ float cpw[64];     // pw_w (8,8)
__constant__ float cb1[16];
__constant__ float cgam[8], cbet[8], cdwb[8], cpwb[8];
__constant__ ULL   cb2p[24];    // b2 (48) as pairs

// ---- packed f32x2 helpers (sm_103a) ----
__device__ __forceinline__ ULL pk(float a, float b) {
    ULL r; asm("mov.b64 %0,{%1,%2};" : "=l"(r) : "f"(a), "f"(b)); return r;
}
__device__ __forceinline__ void upk(ULL v, float& a, float& b) {
    asm("mov.b64 {%0,%1},%2;" : "=f"(a), "=f"(b) : "l"(v));
}
__device__ __forceinline__ ULL f2fma(ULL a, ULL b, ULL c) {
    ULL d; asm("fma.rn.f32x2 %0,%1,%2,%3;" : "=l"(d) : "l"(a), "l"(b), "l"(c)); return d;
}

__device__ __forceinline__ float gelu_exact(float v) {
    return 0.5f * v * (1.0f + erff(v * 0.70710678118654752f));
}

// ---------------------------------------------------------------------------
__global__ void __launch_bounds__(256) kF(const float* __restrict__ x,
                                          float* __restrict__ out) {
    // ring: [slot][c][col]; col 0 and 257 are zero halo, padded to 264
    __shared__ __align__(16) float ns[4][8][264];

    int t  = threadIdx.x;                 // image column w
    int b_ = blockIdx.x >> 5;
    int h0 = (blockIdx.x & 31) << 3;      // 8 output rows per block
    const float* xb = x   + (size_t)b_ * 48 * HW;
    float*       ob = out + (size_t)b_ * 48 * HW;

    // zero the column halos once (visible after first __syncthreads)
    if (t < 64) {
        int s = t >> 4, c = (t >> 1) & 7, col = (t & 1) ? 257 : 0;
        ns[s][c][col] = 0.f;
    }

    float x1p[8], x1c[8];
#pragma unroll
    for (int c = 0; c < 8; c++) x1p[c] = 0.f;

#pragma unroll 1
    for (int i = 0; i < 10; i++) {
        int ra = h0 - 1 + i;              // stage-A row (halo included)
        int sl = i & 3;

        if ((unsigned)ra < 256u) {
            // ---- stage-A: GEMM1 (LDCU weights) ----
            const float4* xp = (const float4*)(xb + (size_t)((ra << 8) + t) * 48);
            ULL acc[8];
#pragma unroll
            for (int j = 0; j < 8; j++) acc[j] = 0ULL;
#pragma unroll
            for (int f = 0; f < 12; f++) {
                float4 v = xp[f];
                float kv[4] = {v.x, v.y, v.z, v.w};
#pragma unroll
                for (int q = 0; q < 4; q++) {
                    ULL bx = pk(kv[q], kv[q]);
#pragma unroll
                    for (int j = 0; j < 8; j++)
                        acc[j] = f2fma(bx, cW1p[(f * 4 + q) * 8 + j], acc[j]);
                }
            }
            float h[16];
#pragma unroll
            for (int j = 0; j < 8; j++) upk(acc[j], h[2 * j], h[2 * j + 1]);
#pragma unroll
            for (int k = 0; k < 16; k++) h[k] = gelu_exact(gelu_exact(h[k] + cb1[k]));

#pragma unroll
            for (int c = 0; c < 8; c++) x1c[c] = h[c];

            // layernorm over h[8..15] -> ring
            float m = 0.f;
#pragma unroll
            for (int c = 0; c < 8; c++) m += h[8 + c];
            m *= 0.125f;
            float var = 0.f;
#pragma unroll
            for (int c = 0; c < 8; c++) { float d = h[8 + c] - m; var += d * d; }
            float inv = rsqrtf(var * 0.125f + 1e-5f);
#pragma unroll
            for (int c = 0; c < 8; c++)
                ns[sl][c][1 + t] = (h[8 + c] - m) * inv * cgam[c] + cbet[c];
        } else {
            // SAME-padding halo row: zeros
#pragma unroll
            for (int c = 0; c < 8; c++) { ns[sl][c][1 + t] = 0.f; x1c[c] = 0.f; }
        }

        __syncthreads();

        if (i >= 2) {
            // ---- stage-B for output row ro (rows ro-1, ro, ro+1 in ring) ----
            int ro = h0 + i - 2;
            int s0 = (i - 2) & 3, s1 = (i - 1) & 3, s2 = sl;

            float sp[8], nc[8];
#pragma unroll
            for (int c = 0; c < 8; c++) {
                float a;
                a  = ns[s0][c][t]     * cdw[c * 9 + 0];
                a += ns[s0][c][t + 1] * cdw[c * 9 + 1];
                a += ns[s0][c][t + 2] * cdw[c * 9 + 2];
                a += ns[s1][c][t]     * cdw[c * 9 + 3];
                float ctr = ns[s1][c][t + 1];
                a += ctr              * cdw[c * 9 + 4];
                a += ns[s1][c][t + 2] * cdw[c * 9 + 5];
                a += ns[s2][c][t]     * cdw[c * 9 + 6];
                a += ns[s2][c][t + 1] * cdw[c * 9 + 7];
                a += ns[s2][c][t + 2] * cdw[c * 9 + 8];
                sp[c] = a + cdwb[c];
                nc[c] = ctr;
            }

            float g[8];
#pragma unroll
            for (int c = 0; c < 8; c++) {
                float a = cpwb[c];
#pragma unroll
                for (int c2 = 0; c2 < 8; c2++)
                    a = fmaf(cpw[c * 8 + c2], nc[c2], a);
                g[c] = x1p[c] * sp[c] * a;      // gate = x1 * sp * ch
            }

            // GEMM2: out[d] = sum_c g[c]*W2[c][d] + b2[d], d packed in pairs
            size_t obase = ((size_t)ro << 8) + (size_t)t;
#pragma unroll
            for (int half = 0; half < 2; half++) {
                ULL o[12];
#pragma unroll
                for (int dd = 0; dd < 12; dd++) o[dd] = cb2p[half * 12 + dd];
#pragma unroll
                for (int c = 0; c < 8; c++) {
                    ULL gb = pk(g[c], g[c]);
#pragma unroll
                    for (int dd = 0; dd < 12; dd++)
                        o[dd] = f2fma(gb, cW2p[c * 24 + half * 12 + dd], o[dd]);
                }
#pragma unroll
                for (int dd = 0; dd < 12; dd++) {
                    float pa, pb; upk(o[dd], pa, pb);
                    int d = half * 24 + 2 * dd;
                    ob[((size_t)d << 16) + obase]       = pa;
                    ob[((size_t)(d + 1) << 16) + obase] = pb;
                }
            }
        }

        // rotate x1 (row computed this iter becomes next iter's output row)
#pragma unroll
        for (int c = 0; c < 8; c++) x1p[c] = x1c[c];
    }
}

// ---------------------------------------------------------------------------
extern "C" void kernel_launch(void* const* d_in, const int* in_sizes, int n_in,
                              void* d_out, int out_size) {
    const float* x = (const float*)d_in[0];
    float* out = (float*)d_out;

    // weights -> constant memory (async D2D; graph-capturable memcpy nodes)
    cudaMemcpyToSymbolAsync(cW1p, d_in[1], 768 * 4, 0, cudaMemcpyDeviceToDevice);
    cudaMemcpyToSymbolAsync(cb1,  d_in[2], 16 * 4,  0, cudaMemcpyDeviceToDevice);
    cudaMemcpyToSymbolAsync(cgam, d_in[3], 8 * 4,   0, cudaMemcpyDeviceToDevice);
    cudaMemcpyToSymbolAsync(cbet, d_in[4], 8 * 4,   0, cudaMemcpyDeviceToDevice);
    cudaMemcpyToSymbolAsync(cdw,  d_in[5], 72 * 4,  0, cudaMemcpyDeviceToDevice);
    cudaMemcpyToSymbolAsync(cdwb, d_in[6], 8 * 4,   0, cudaMemcpyDeviceToDevice);
    cudaMemcpyToSymbolAsync(cpw,  d_in[7], 64 * 4,  0, cudaMemcpyDeviceToDevice);
    cudaMemcpyToSymbolAsync(cpwb, d_in[8], 8 * 4,   0, cudaMemcpyDeviceToDevice);
    cudaMemcpyToSymbolAsync(cW2p, d_in[9], 384 * 4, 0, cudaMemcpyDeviceToDevice);
    cudaMemcpyToSymbolAsync(cb2p, d_in[10], 48 * 4, 0, cudaMemcpyDeviceToDevice);

    // 16 batches x 32 row-tiles = 512 blocks, 256 threads (one per column)
    kF<<<512, 256>>>(x, out);
}

// round 9
// speedup vs baseline: 1.8942x; 1.8942x over previous
#include <cuda_runtime.h>
#include <math.h>

typedef unsigned long long ULL;

// ---------------------------------------------------------------------------
// B=16, dim=48, hid=16, C=8, H=W=256, HW=65536. Total pixels = 1,048,576.
// R2-proven two-kernel architecture; single change vs R2: erff -> gelu_fast.
// ---------------------------------------------------------------------------
#define HW 65536
#define NB 16

// Scratch (allocation-free rule: __device__ globals). 33.5 MB each.
__device__ __align__(16) float g_n [NB * 8 * HW];   // planar (B, C, HW) — LN'd x2
__device__ __align__(16) float g_x1[NB * HW * 8];   // (B, HW, C) — gate branch

// Weights in constant memory (compile-time-indexed -> LDCU uniform port)
__constant__ ULL   cW1p[384];   // W1 (48,16) as pairs [k*8 + j2]
__constant__ ULL   cW2p[192];   // W2 (8,48)  as pairs [c*24 + d2]
__constant__ float cdw[72];     // dw_w (8,1,3,3)
__constant__ float cpw[64];     // pw_w (8,8)
__constant__ float cb1[16];
__constant__ float cgam[8], cbet[8], cdwb[8], cpwb[8];
__constant__ ULL   cb2p[24];    // b2 (48) as pairs

// ---- packed f32x2 helpers (sm_103a) ----
__device__ __forceinline__ ULL pk(float a, float b) {
    ULL r; asm("mov.b64 %0,{%1,%2};" : "=l"(r) : "f"(a), "f"(b)); return r;
}
__device__ __forceinline__ void upk(ULL v, float& a, float& b) {
    asm("mov.b64 {%0,%1},%2;" : "=f"(a), "=f"(b) : "l"(v));
}
__device__ __forceinline__ ULL f2fma(ULL a, ULL b, ULL c) {
    ULL d; asm("fma.rn.f32x2 %0,%1,%2,%3;" : "=l"(d) : "l"(a), "l"(b), "l"(c)); return d;
}
__device__ __forceinline__ ULL f2mul(ULL a, ULL b) {
    ULL d; asm("mul.rn.f32x2 %0,%1,%2;" : "=l"(d) : "l"(a), "l"(b)); return d;
}
__device__ __forceinline__ ULL f2add(ULL a, ULL b) {
    ULL d; asm("add.rn.f32x2 %0,%1,%2;" : "=l"(d) : "l"(a), "l"(b)); return d;
}

// Fast GELU: erf via A&S 7.1.26 (|abs err| <= 1.5e-7), MUFU rcp/exp.
// Verified in R6 bench: overall rel_err 4.48e-7.
__device__ __forceinline__ float gelu_fast(float v) {
    float x  = v * 0.70710678118654752f;
    float ax = fabsf(x);
    float t  = __frcp_rn(fmaf(0.3275911f, ax, 1.0f));
    float p  = 1.061405429f;
    p = fmaf(p, t, -1.453152027f);
    p = fmaf(p, t,  1.421413741f);
    p = fmaf(p, t, -0.284496736f);
    p = fmaf(p, t,  0.254829592f);
    p *= t;
    float e  = __expf(-x * x);
    float er = fmaf(-p, e, 1.0f);        // erf(|x|)
    er = copysignf(er, v);
    return 0.5f * v * (1.0f + er);
}

// ---------------------------------------------------------------------------
// Kernel A (R2-proven structure): coalesced smem staging of x (rotation
// swizzle), W1 from constant (LDCU), per-pixel GEMM1 + double GELU + LN.
// 128 px/block, 8192 blocks.
// ---------------------------------------------------------------------------
__global__ void __launch_bounds__(128) kA(const float* __restrict__ x) {
    __shared__ __align__(16) float4 xs4[128 * 12];   // 24 KB

    int t = threadIdx.x;
    size_t Pbase = (size_t)blockIdx.x * 128;
    const float4* gx = (const float4*)(x + Pbase * 48);

#pragma unroll
    for (int i = 0; i < 12; i++) {
        int idx = i * 128 + t;          // 0..1535
        int p = idx / 12;
        int f = idx - p * 12;
        int fr = f + p; fr %= 12;
        xs4[p * 12 + fr] = gx[idx];
    }
    __syncthreads();

    // GEMM1: 8 f32x2 accumulators (16 outputs)
    ULL acc[8];
#pragma unroll
    for (int j = 0; j < 8; j++) acc[j] = 0ULL;

    int r0 = t % 12;
#pragma unroll
    for (int f = 0; f < 12; f++) {
        int fr = f + r0; if (fr >= 12) fr -= 12;
        float4 v = xs4[t * 12 + fr];
        float kv[4] = {v.x, v.y, v.z, v.w};
#pragma unroll
        for (int q = 0; q < 4; q++) {
            int k = f * 4 + q;
            ULL bx = pk(kv[q], kv[q]);
#pragma unroll
            for (int j = 0; j < 8; j++)
                acc[j] = f2fma(bx, cW1p[k * 8 + j], acc[j]);
        }
    }

    // epilogue
    float h[16];
#pragma unroll
    for (int j = 0; j < 8; j++) upk(acc[j], h[2 * j], h[2 * j + 1]);
#pragma unroll
    for (int i = 0; i < 16; i++) h[i] = gelu_fast(gelu_fast(h[i] + cb1[i]));

    size_t P = Pbase + (size_t)t;
    ((float4*)g_x1)[P * 2]     = make_float4(h[0], h[1], h[2], h[3]);
    ((float4*)g_x1)[P * 2 + 1] = make_float4(h[4], h[5], h[6], h[7]);

    float m = 0.0f;
#pragma unroll
    for (int c = 0; c < 8; c++) m += h[8 + c];
    m *= 0.125f;
    float var = 0.0f;
#pragma unroll
    for (int c = 0; c < 8; c++) { float d = h[8 + c] - m; var += d * d; }
    var *= 0.125f;
    float inv = rsqrtf(var + 1e-5f);

    size_t b_ = P >> 16, pp = P & 65535;
    float* nb = g_n + (b_ << 19) + pp;
#pragma unroll
    for (int c = 0; c < 8; c++)
        nb[(size_t)c << 16] = (h[8 + c] - m) * inv * cgam[c] + cbet[c];
}

// ---------------------------------------------------------------------------
// Kernel B (R3/R7-proven, constant weights): one block = one (b,h) row;
// 128 threads, pixel pair (2t, 2t+1) packed in f32x2 lanes.
// ---------------------------------------------------------------------------
__global__ void __launch_bounds__(128) kB(float* __restrict__ out) {
    __shared__ __align__(16) float ns[8][3][264];   // halo cols 0 and 257 zeroed

    int t = threadIdx.x;
    int b_ = blockIdx.x >> 8;
    int h  = blockIdx.x & 255;
    int w0 = 2 * t;

    // prefetch x1 (DRAM latency hidden behind smem fill + conv)
    size_t P0 = ((size_t)b_ << 16) + ((size_t)h << 8) + (size_t)w0;
    const float4* x1v = (const float4*)(g_x1 + P0 * 8);
    float4 XA = x1v[0], XB = x1v[1], XC = x1v[2], XD = x1v[3];

    const float* nbase = g_n + ((size_t)b_ << 19);
#pragma unroll
    for (int c = 0; c < 8; c++) {
#pragma unroll
        for (int r = 0; r < 3; r++) {
            int hs = h + r - 1;
            float2 v = make_float2(0.f, 0.f);
            if ((unsigned)hs < 256u)
                v = ((const float2*)(nbase + ((size_t)c << 16) + ((size_t)hs << 8)))[t];
            ns[c][r][1 + w0] = v.x;
            ns[c][r][2 + w0] = v.y;
        }
    }
    if (t == 0) {
#pragma unroll
        for (int c = 0; c < 8; c++)
#pragma unroll
            for (int r = 0; r < 3; r++) { ns[c][r][0] = 0.f; ns[c][r][257] = 0.f; }
    }
    __syncthreads();

    // depthwise 3x3 (SAME)
    ULL spp[8], ncp[8];
#pragma unroll
    for (int c = 0; c < 8; c++) {
        ULL acc = 0ULL, center = 0ULL;
#pragma unroll
        for (int r = 0; r < 3; r++) {
            ULL v01 = *(const ULL*)&ns[c][r][w0];       // (w0-1, w0)
            ULL v23 = *(const ULL*)&ns[c][r][w0 + 2];   // (w0+1, w0+2)
            ULL v12 = (v01 >> 32) | (v23 << 32);        // (w0,   w0+1)
            float wa = cdw[c * 9 + r * 3 + 0];
            float wb = cdw[c * 9 + r * 3 + 1];
            float wc = cdw[c * 9 + r * 3 + 2];
            acc = f2fma(v01, pk(wa, wa), acc);
            acc = f2fma(v12, pk(wb, wb), acc);
            acc = f2fma(v23, pk(wc, wc), acc);
            if (r == 1) center = v12;
        }
        spp[c] = f2add(acc, pk(cdwb[c], cdwb[c]));
        ncp[c] = center;
    }

    // pointwise 1x1
    ULL chp[8];
#pragma unroll
    for (int c = 0; c < 8; c++) {
        ULL a = pk(cpwb[c], cpwb[c]);
#pragma unroll
        for (int c2 = 0; c2 < 8; c2++) {
            float w = cpw[c * 8 + c2];
            a = f2fma(ncp[c2], pk(w, w), a);
        }
        chp[c] = a;
    }

    // gate: g = x1 * sp * ch   (lanes = the two pixels)
    float x10[8] = {XA.x, XA.y, XA.z, XA.w, XB.x, XB.y, XB.z, XB.w};
    float x11[8] = {XC.x, XC.y, XC.z, XC.w, XD.x, XD.y, XD.z, XD.w};
    ULL gp[8];
#pragma unroll
    for (int c = 0; c < 8; c++)
        gp[c] = f2mul(pk(x10[c], x11[c]), f2mul(spp[c], chp[c]));

    // GEMM2 in 4 quarters of 12 outputs (lower live regs)
    float* ob = out + (((size_t)b_ * 48) << 16) + ((size_t)h << 8) + (size_t)w0;
#pragma unroll
    for (int q = 0; q < 4; q++) {
        ULL o0[6], o1[6];
#pragma unroll
        for (int j = 0; j < 6; j++) { o0[j] = cb2p[q * 6 + j]; o1[j] = o0[j]; }
#pragma unroll
        for (int c = 0; c < 8; c++) {
            float g0, g1; upk(gp[c], g0, g1);
            ULL gb0 = pk(g0, g0), gb1 = pk(g1, g1);
#pragma unroll
            for (int j = 0; j < 6; j++) {
                ULL wv = cW2p[c * 24 + q * 6 + j];
                o0[j] = f2fma(gb0, wv, o0[j]);
                o1[j] = f2fma(gb1, wv, o1[j]);
            }
        }
#pragma unroll
        for (int j = 0; j < 6; j++) {
            float p00, p01, p10, p11;
            upk(o0[j], p00, p01);   // px0: d = d0, d0+1
            upk(o1[j], p10, p11);   // px1
            int d0 = q * 12 + 2 * j;
            *((float2*)(ob + ((size_t)d0 << 16)))       = make_float2(p00, p10);
            *((float2*)(ob + ((size_t)(d0 + 1) << 16))) = make_float2(p01, p11);
        }
    }
}

// ---------------------------------------------------------------------------
extern "C" void kernel_launch(void* const* d_in, const int* in_sizes, int n_in,
                              void* d_out, int out_size) {
    const float* x = (const float*)d_in[0];
    float* out = (float*)d_out;

    // weights -> constant memory (async D2D; graph-capturable memcpy nodes)
    cudaMemcpyToSymbolAsync(cW1p, d_in[1], 768 * 4, 0, cudaMemcpyDeviceToDevice);
    cudaMemcpyToSymbolAsync(cb1,  d_in[2], 16 * 4,  0, cudaMemcpyDeviceToDevice);
    cudaMemcpyToSymbolAsync(cgam, d_in[3], 8 * 4,   0, cudaMemcpyDeviceToDevice);
    cudaMemcpyToSymbolAsync(cbet, d_in[4], 8 * 4,   0, cudaMemcpyDeviceToDevice);
    cudaMemcpyToSymbolAsync(cdw,  d_in[5], 72 * 4,  0, cudaMemcpyDeviceToDevice);
    cudaMemcpyToSymbolAsync(cdwb, d_in[6], 8 * 4,   0, cudaMemcpyDeviceToDevice);
    cudaMemcpyToSymbolAsync(cpw,  d_in[7], 64 * 4,  0, cudaMemcpyDeviceToDevice);
    cudaMemcpyToSymbolAsync(cpwb, d_in[8], 8 * 4,   0, cudaMemcpyDeviceToDevice);
    cudaMemcpyToSymbolAsync(cW2p, d_in[9], 384 * 4, 0, cudaMemcpyDeviceToDevice);
    cudaMemcpyToSymbolAsync(cb2p, d_in[10], 48 * 4, 0, cudaMemcpyDeviceToDevice);

    kA<<<8192, 128>>>(x);
    kB<<<4096, 128>>>(out);
}